// round 11
// baseline (speedup 1.0000x reference)
#include <cuda_runtime.h>
#include <cstdint>

#define NB 2
#define NT 2048
#define ND 1024
#define NH 16
#define NHD 64
#define NM (NB * NT) /* 4096 rows */

// Scratch (device globals: allocation-free per harness rules)
__device__ float g_q[(size_t)NB * NH * NT * NHD];
__device__ float g_k[(size_t)NB * NH * NT * NHD];
__device__ float g_v[(size_t)NB * NH * NT * NHD];
__device__ float g_y[(size_t)NM * ND];

// ---------------------------------------------------------------------------
// tf32 / math helpers
// ---------------------------------------------------------------------------
__device__ __forceinline__ uint32_t f2tf32(float x) {
    uint32_t r;
    asm("cvt.rna.tf32.f32 %0, %1;" : "=r"(r) : "f"(x));
    return r;
}

__device__ __forceinline__ float ex2(float x) {
    float y;
    asm("ex2.approx.ftz.f32 %0, %1;" : "=f"(y) : "f"(x));
    return y;
}

__device__ __forceinline__ void mma_tf32(float* c, const uint32_t* a,
                                         const uint32_t* b) {
    asm volatile(
        "mma.sync.aligned.m16n8k8.row.col.f32.tf32.tf32.f32 "
        "{%0,%1,%2,%3}, {%4,%5,%6,%7}, {%8,%9}, {%0,%1,%2,%3};\n"
        : "+f"(c[0]), "+f"(c[1]), "+f"(c[2]), "+f"(c[3])
        : "r"(a[0]), "r"(a[1]), "r"(a[2]), "r"(a[3]), "r"(b[0]), "r"(b[1]));
}

// ldmatrix x4: four 8x8 b16 matrices == four 8x4 b32 matrices.
__device__ __forceinline__ void ldsm_x4(uint32_t* d, uint32_t addr) {
    asm volatile(
        "ldmatrix.sync.aligned.m8n8.x4.shared.b16 {%0,%1,%2,%3}, [%4];"
        : "=r"(d[0]), "=r"(d[1]), "=r"(d[2]), "=r"(d[3])
        : "r"(addr));
}

// ---------------------------------------------------------------------------
// tf32 tensor-core GEMM (R10, unchanged): C[m,n] = A[m,:]·W[n,:] + bias[n]
// CTA 128x128, K-step 16, 128 threads, warp tile 64x64, ldmatrix, BKP=20,
// double-buffered smem. HEADS epilogue pre-rounds outputs to tf32.
// ---------------------------------------------------------------------------
#define BKP 20
#define GBUF (128 * BKP * 4) /* 10240 B per buffer */

template <bool HEADS>
__global__ __launch_bounds__(128, 2)
void gemm_kernel(const float* __restrict__ A,
                 const float* __restrict__ W0, const float* __restrict__ B0,
                 const float* __restrict__ W1, const float* __restrict__ B1,
                 const float* __restrict__ W2, const float* __restrict__ B2,
                 float* __restrict__ Cplain)
{
    const float* W;
    const float* bias;
    float* outq = nullptr;
    if (HEADS) {
        int z = blockIdx.z;
        W    = (z == 0) ? W0 : (z == 1) ? W1 : W2;
        bias = (z == 0) ? B0 : (z == 1) ? B1 : B2;
        outq = (z == 0) ? g_q : (z == 1) ? g_k : g_v;
    } else {
        W = W0; bias = B0;
    }
    const float* Ap = HEADS ? A : g_y;

    __shared__ uint32_t As[2][128][BKP];
    __shared__ uint32_t Bs[2][128][BKP];

    const int tid  = threadIdx.x;
    const int lane = tid & 31;
    const int wid  = tid >> 5;
    const int m0 = blockIdx.y * 128;
    const int n0 = blockIdx.x * 128;
    const int warp_m = (wid >> 1) * 64;
    const int warp_n = (wid & 1) * 64;
    const int r = lane >> 2;
    const int qc = lane & 3;

    const int g  = lane >> 3;
    const int lr = lane & 7;
    const uint32_t aBaseS =
        (uint32_t)__cvta_generic_to_shared(&As[0][0][0]);
    const uint32_t bBaseS =
        (uint32_t)__cvta_generic_to_shared(&Bs[0][0][0]);
    const uint32_t aAddr0 =
        aBaseS + (((warp_m + (g & 1) * 8 + lr) * BKP + (g >> 1) * 4) << 2);
    const uint32_t bAddr0 =
        bBaseS + (((warp_n + (g >> 1) * 8 + lr) * BKP + (g & 1) * 4) << 2);

    float acc[4][8][4];
#pragma unroll
    for (int mi = 0; mi < 4; mi++)
#pragma unroll
        for (int ni = 0; ni < 8; ni++)
#pragma unroll
            for (int e = 0; e < 4; e++) acc[mi][ni][e] = 0.f;

    const float* aBase = Ap + (size_t)m0 * ND;
    const float* wBase = W  + (size_t)n0 * ND;

    float4 pa[4], pb[4];
#pragma unroll
    for (int i = 0; i < 4; i++) {
        int idx = tid + i * 128;
        int row = idx >> 2;
        int c4  = (idx & 3) * 4;
        pa[i] = *(const float4*)(aBase + (size_t)row * ND + c4);
        pb[i] = *(const float4*)(wBase + (size_t)row * ND + c4);
    }
#pragma unroll
    for (int i = 0; i < 4; i++) {
        int idx = tid + i * 128;
        int row = idx >> 2;
        int c4  = (idx & 3) * 4;
        uint4 u;
        u.x = f2tf32(pa[i].x); u.y = f2tf32(pa[i].y);
        u.z = f2tf32(pa[i].z); u.w = f2tf32(pa[i].w);
        *(uint4*)&As[0][row][c4] = u;
        u.x = f2tf32(pb[i].x); u.y = f2tf32(pb[i].y);
        u.z = f2tf32(pb[i].z); u.w = f2tf32(pb[i].w);
        *(uint4*)&Bs[0][row][c4] = u;
    }
    __syncthreads();

    int buf = 0;
    for (int k0 = 0; k0 < ND; k0 += 16) {
        const bool more = (k0 + 16 < ND);
        if (more) {
            const int kn = k0 + 16;
#pragma unroll
            for (int i = 0; i < 4; i++) {
                int idx = tid + i * 128;
                int row = idx >> 2;
                int c4  = (idx & 3) * 4;
                pa[i] = *(const float4*)(aBase + (size_t)row * ND + kn + c4);
                pb[i] = *(const float4*)(wBase + (size_t)row * ND + kn + c4);
            }
        }

        const uint32_t bofs = (uint32_t)buf * GBUF;
#pragma unroll
        for (int t = 0; t < 2; t++) {
            uint32_t afr[4][4], bfr[4][4];
#pragma unroll
            for (int mi = 0; mi < 4; mi++)
                ldsm_x4(afr[mi],
                        aAddr0 + bofs + (uint32_t)(mi * 16 * BKP * 4 + t * 32));
#pragma unroll
            for (int nj = 0; nj < 4; nj++)
                ldsm_x4(bfr[nj],
                        bAddr0 + bofs + (uint32_t)(nj * 16 * BKP * 4 + t * 32));
#pragma unroll
            for (int mi = 0; mi < 4; mi++)
#pragma unroll
                for (int nj = 0; nj < 4; nj++) {
                    mma_tf32(acc[mi][2 * nj + 0], afr[mi], &bfr[nj][0]);
                    mma_tf32(acc[mi][2 * nj + 1], afr[mi], &bfr[nj][2]);
                }
        }

        if (more) {
            const int nb = buf ^ 1;
#pragma unroll
            for (int i = 0; i < 4; i++) {
                int idx = tid + i * 128;
                int row = idx >> 2;
                int c4  = (idx & 3) * 4;
                uint4 u;
                u.x = f2tf32(pa[i].x); u.y = f2tf32(pa[i].y);
                u.z = f2tf32(pa[i].z); u.w = f2tf32(pa[i].w);
                *(uint4*)&As[nb][row][c4] = u;
                u.x = f2tf32(pb[i].x); u.y = f2tf32(pb[i].y);
                u.z = f2tf32(pb[i].z); u.w = f2tf32(pb[i].w);
                *(uint4*)&Bs[nb][row][c4] = u;
            }
            __syncthreads();
            buf = nb;
        }
    }

#pragma unroll
    for (int mi = 0; mi < 4; mi++) {
#pragma unroll
        for (int ni = 0; ni < 8; ni++) {
#pragma unroll
            for (int half = 0; half < 2; half++) {
                int m = m0 + warp_m + mi * 16 + r + half * 8;
                int nA = n0 + warp_n + ni * 8 + 2 * qc;
                float v0 = acc[mi][ni][half * 2 + 0] + bias[nA];
                float v1 = acc[mi][ni][half * 2 + 1] + bias[nA + 1];
                if (HEADS) {
                    int bb = m >> 11;
                    int tt = m & (NT - 1);
                    int h  = nA >> 6;
                    int hd = nA & (NHD - 1);
                    float* dst = outq +
                        (((size_t)bb * NH + h) * NT + tt) * NHD + hd;
                    dst[0] = __uint_as_float(f2tf32(v0));
                    dst[1] = __uint_as_float(f2tf32(v1));
                } else {
                    float* dst = Cplain + (size_t)m * ND + nA;
                    dst[0] = v0; dst[1] = v1;
                }
            }
        }
    }
}

// ---------------------------------------------------------------------------
// Tensor-core tf32 flash attention, causal. R11: 32 q-rows per warp
// (4 warps, 128 threads, CTA q-tile 128). Each K/V fragment ldsm now feeds
// TWO 16-row MMA halves -> per-tile smem fragment traffic 288KB -> 160KB.
// Next-tile K/V prefetch issued after softmax (sfr regs dead) to fit the
// 252-reg budget. Accumulation order per output unchanged -> bit-identical.
// ---------------------------------------------------------------------------
#define AST 68  /* smem row stride in words */
/* Ks: 64 rows, Vt: 64 rows, Ps: 128 rows */
#define ATTN_SMEM (256 * AST * 4)  /* 69632 B */

__global__ __launch_bounds__(128, 2)
void attn_tc_kernel()
{
    extern __shared__ uint32_t smraw[];
    uint32_t (*Ks)[AST] = (uint32_t(*)[AST])smraw;
    uint32_t (*Vt)[AST] = (uint32_t(*)[AST])(smraw + 64 * AST);
    uint32_t (*Ps)[AST] = (uint32_t(*)[AST])(smraw + 128 * AST);

    const int bh   = blockIdx.y;
    const int q0   = blockIdx.x * 128;
    const int tid  = threadIdx.x;
    const int lane = tid & 31;
    const int warp = tid >> 5;     // 0..3
    const int r    = lane >> 2;    // 0..7
    const int c    = lane & 3;     // 0..3
    const int w32  = warp * 32;
    const int g    = lane >> 3;    // ldmatrix group
    const int lr   = lane & 7;

    const uint32_t* Qb = (const uint32_t*)g_q + (size_t)bh * NT * NHD;
    const uint32_t* Kb = (const uint32_t*)g_k + (size_t)bh * NT * NHD;
    const uint32_t* Vb = (const uint32_t*)g_v + (size_t)bh * NT * NHD;

    const uint32_t psBase = (uint32_t)__cvta_generic_to_shared(&Ps[0][0]);
    const uint32_t ksBase = (uint32_t)__cvta_generic_to_shared(&Ks[0][0]);
    const uint32_t vtBase = (uint32_t)__cvta_generic_to_shared(&Vt[0][0]);
    uint32_t aAddr[2];
#pragma unroll
    for (int h = 0; h < 2; h++)
        aAddr[h] = psBase +
            (((w32 + h * 16 + (g & 1) * 8 + lr) * AST + (g >> 1) * 4) << 2);
    const uint32_t kAddr =
        ksBase + ((((g >> 1) * 8 + lr) * AST + (g & 1) * 4) << 2);
    const uint32_t vAddr =
        vtBase + ((((g >> 1) * 8 + lr) * AST + (g & 1) * 4) << 2);

    // ---- stage Q tile (pre-rounded tf32 bits) through Ps ----
#pragma unroll
    for (int i = 0; i < 16; i++) {
        int idx = tid + i * 128;        // 0..2047
        int row = idx >> 4;             // 0..127
        int c4  = (idx & 15) * 4;
        *(uint4*)&Ps[row][c4] =
            *(const uint4*)(Qb + (size_t)(q0 + row) * NHD + c4);
    }
    __syncthreads();

    uint32_t qf[2][8][4];
#pragma unroll
    for (int h = 0; h < 2; h++)
#pragma unroll
        for (int kc = 0; kc < 8; kc++)
            ldsm_x4(qf[h][kc], aAddr[h] + kc * 32);
    __syncthreads();

    float o[2][8][4];
#pragma unroll
    for (int h = 0; h < 2; h++)
#pragma unroll
        for (int nt = 0; nt < 8; nt++)
#pragma unroll
            for (int e = 0; e < 4; e++) o[h][nt][e] = 0.f;

    float mv[2][2], lv[2][2];
#pragma unroll
    for (int h = 0; h < 2; h++) {
        mv[h][0] = mv[h][1] = -1e30f;
        lv[h][0] = lv[h][1] = 0.f;
    }
    const float C2 = 0.18033688f;   // 0.125 * log2(e)

    const int ktiles = blockIdx.x * 2 + 2;

    // per-thread staging coordinates (128 threads)
    const int kRow = tid >> 4;            // 0..7, rows kRow + i*8
    const int kC4  = (tid & 15) * 4;
    const int vD   = tid & 63;            // Vt: dim
    const int vK0  = (tid >> 6) * 4;      // Vt: key base, keys vK0 + i*8

    // ---- prefetch tile 0 into registers ----
    uint4 kq[8];
    uint32_t vq[32];
#pragma unroll
    for (int i = 0; i < 8; i++) {
        kq[i] = *(const uint4*)(Kb + (size_t)(kRow + i * 8) * NHD + kC4);
#pragma unroll
        for (int j = 0; j < 4; j++)
            vq[i * 4 + j] = Vb[(size_t)(vK0 + i * 8 + j) * NHD + vD];
    }

    for (int kt = 0; kt < ktiles; kt++) {
        const int kbase = kt * 64;
        __syncthreads();   // all warps done reading Ks/Vt from prev tile
#pragma unroll
        for (int i = 0; i < 8; i++) {
            *(uint4*)&Ks[kRow + i * 8][kC4] = kq[i];
            uint4 u;
            u.x = vq[i * 4 + 0]; u.y = vq[i * 4 + 1];
            u.z = vq[i * 4 + 2]; u.w = vq[i * 4 + 3];
            *(uint4*)&Vt[vD][vK0 + i * 8] = u;
        }
        __syncthreads();

        // ---- S = Q @ K^T : each K frag feeds both 16-row halves ----
        float sfr[2][8][4];
#pragma unroll
        for (int h = 0; h < 2; h++)
#pragma unroll
            for (int nt = 0; nt < 8; nt++)
                sfr[h][nt][0] = sfr[h][nt][1] =
                sfr[h][nt][2] = sfr[h][nt][3] = 0.f;
#pragma unroll
        for (int kc = 0; kc < 8; kc++) {
#pragma unroll
            for (int ng = 0; ng < 4; ng++) {
                uint32_t bk[4];
                ldsm_x4(bk, kAddr + (uint32_t)(ng * 16 * AST * 4 + kc * 32));
                mma_tf32(sfr[0][2 * ng + 0], qf[0][kc], &bk[0]);
                mma_tf32(sfr[0][2 * ng + 1], qf[0][kc], &bk[2]);
                mma_tf32(sfr[1][2 * ng + 0], qf[1][kc], &bk[0]);
                mma_tf32(sfr[1][2 * ng + 1], qf[1][kc], &bk[2]);
            }
        }

        // ---- causal mask (diagonal tiles of this warp only) ----
        if (kbase + 63 > q0 + w32) {
#pragma unroll
            for (int h = 0; h < 2; h++) {
                const int gr0 = q0 + w32 + h * 16 + r;
                const int gr1 = gr0 + 8;
#pragma unroll
                for (int nt = 0; nt < 8; nt++) {
                    int col = kbase + nt * 8 + 2 * c;
                    if (col > gr0)     sfr[h][nt][0] = -1e30f;
                    if (col + 1 > gr0) sfr[h][nt][1] = -1e30f;
                    if (col > gr1)     sfr[h][nt][2] = -1e30f;
                    if (col + 1 > gr1) sfr[h][nt][3] = -1e30f;
                }
            }
        }

        // ---- online softmax (per half) ----
#pragma unroll
        for (int h = 0; h < 2; h++) {
            float mx0 = -1e30f, mx1 = -1e30f;
#pragma unroll
            for (int nt = 0; nt < 8; nt++) {
                mx0 = fmaxf(mx0, fmaxf(sfr[h][nt][0], sfr[h][nt][1]));
                mx1 = fmaxf(mx1, fmaxf(sfr[h][nt][2], sfr[h][nt][3]));
            }
            mx0 = fmaxf(mx0, __shfl_xor_sync(0xffffffffu, mx0, 1));
            mx0 = fmaxf(mx0, __shfl_xor_sync(0xffffffffu, mx0, 2));
            mx1 = fmaxf(mx1, __shfl_xor_sync(0xffffffffu, mx1, 1));
            mx1 = fmaxf(mx1, __shfl_xor_sync(0xffffffffu, mx1, 2));

            float mn0 = fmaxf(mv[h][0], mx0);
            float mn1 = fmaxf(mv[h][1], mx1);
            float cor0 = ex2((mv[h][0] - mn0) * C2);
            float cor1 = ex2((mv[h][1] - mn1) * C2);
            lv[h][0] *= cor0; lv[h][1] *= cor1;
            mv[h][0] = mn0;   mv[h][1] = mn1;

#pragma unroll
            for (int nt = 0; nt < 8; nt++) {
                float p0 = ex2((sfr[h][nt][0] - mn0) * C2);
                float p1 = ex2((sfr[h][nt][1] - mn0) * C2);
                float p2 = ex2((sfr[h][nt][2] - mn1) * C2);
                float p3 = ex2((sfr[h][nt][3] - mn1) * C2);
                lv[h][0] += p0 + p1;
                lv[h][1] += p2 + p3;
                o[h][nt][0] *= cor0; o[h][nt][1] *= cor0;
                o[h][nt][2] *= cor1; o[h][nt][3] *= cor1;
                uint2 w0; w0.x = f2tf32(p0); w0.y = f2tf32(p1);
                *(uint2*)&Ps[w32 + h * 16 + r][nt * 8 + 2 * c] = w0;
                uint2 w1; w1.x = f2tf32(p2); w1.y = f2tf32(p3);
                *(uint2*)&Ps[w32 + h * 16 + 8 + r][nt * 8 + 2 * c] = w1;
            }
        }
        __syncwarp();   // P slab is warp-private: no CTA barrier needed

        // ---- prefetch next tile (sfr dead; latency hides behind PV) ----
        if (kt + 1 < ktiles) {
            const int nb0 = kbase + 64;
#pragma unroll
            for (int i = 0; i < 8; i++) {
                kq[i] = *(const uint4*)(Kb +
                        (size_t)(nb0 + kRow + i * 8) * NHD + kC4);
#pragma unroll
                for (int j = 0; j < 4; j++)
                    vq[i * 4 + j] =
                        Vb[(size_t)(nb0 + vK0 + i * 8 + j) * NHD + vD];
            }
        }

        // ---- O += P @ V : each V frag feeds both halves ----
#pragma unroll
        for (int kc = 0; kc < 8; kc++) {
            uint32_t ap[2][4];
            ldsm_x4(ap[0], aAddr[0] + kc * 32);
            ldsm_x4(ap[1], aAddr[1] + kc * 32);
#pragma unroll
            for (int ng = 0; ng < 4; ng++) {
                uint32_t bv[4];
                ldsm_x4(bv, vAddr + (uint32_t)(ng * 16 * AST * 4 + kc * 32));
                mma_tf32(o[0][2 * ng + 0], ap[0], &bv[0]);
                mma_tf32(o[0][2 * ng + 1], ap[0], &bv[2]);
                mma_tf32(o[1][2 * ng + 0], ap[1], &bv[0]);
                mma_tf32(o[1][2 * ng + 1], ap[1], &bv[2]);
            }
        }
        __syncwarp();
    }

    // ---- quad-reduce softmax denominators, normalize + store ----
    const int b  = bh >> 4;
    const int h2 = bh & (NH - 1);
#pragma unroll
    for (int h = 0; h < 2; h++) {
        float l0 = lv[h][0], l1 = lv[h][1];
        l0 += __shfl_xor_sync(0xffffffffu, l0, 1);
        l0 += __shfl_xor_sync(0xffffffffu, l0, 2);
        l1 += __shfl_xor_sync(0xffffffffu, l1, 1);
        l1 += __shfl_xor_sync(0xffffffffu, l1, 2);
        float inv0 = 1.f / l0;
        float inv1 = 1.f / l1;
        const int gr0 = q0 + w32 + h * 16 + r;
        const int gr1 = gr0 + 8;
        float* y0 = g_y + ((size_t)b * NT + gr0) * ND + h2 * NHD;
        float* y1 = g_y + ((size_t)b * NT + gr1) * ND + h2 * NHD;
#pragma unroll
        for (int nt = 0; nt < 8; nt++) {
            float2 w0; w0.x = o[h][nt][0] * inv0; w0.y = o[h][nt][1] * inv0;
            *(float2*)(y0 + nt * 8 + 2 * c) = w0;
            float2 w1; w1.x = o[h][nt][2] * inv1; w1.y = o[h][nt][3] * inv1;
            *(float2*)(y1 + nt * 8 + 2 * c) = w1;
        }
    }
}

// ---------------------------------------------------------------------------
extern "C" void kernel_launch(void* const* d_in, const int* in_sizes, int n_in,
                              void* d_out, int out_size)
{
    const float* x  = (const float*)d_in[0];
    const float* Wq = (const float*)d_in[1];
    const float* bq = (const float*)d_in[2];
    const float* Wk = (const float*)d_in[3];
    const float* bk = (const float*)d_in[4];
    const float* Wv = (const float*)d_in[5];
    const float* bv = (const float*)d_in[6];
    const float* Wp = (const float*)d_in[7];
    const float* bp = (const float*)d_in[8];
    float* out = (float*)d_out;

    cudaFuncSetAttribute(attn_tc_kernel,
                         cudaFuncAttributeMaxDynamicSharedMemorySize,
                         ATTN_SMEM);

    dim3 gq(ND / 128, NM / 128, 3);   // 8 x 32 x 3
    gemm_kernel<true><<<gq, 128>>>(x, Wq, bq, Wk, bk, Wv, bv, nullptr);

    dim3 ga(NT / 128, NB * NH);       // 16 x 32
    attn_tc_kernel<<<ga, 128, ATTN_SMEM>>>();

    dim3 gp(ND / 128, NM / 128, 1);   // 8 x 32
    gemm_kernel<false><<<gp, 128>>>(nullptr, Wp, bp, nullptr, nullptr,
                                    nullptr, nullptr, out);
}